// round 4
// baseline (speedup 1.0000x reference)
#include <cuda_runtime.h>

typedef unsigned long long ull;

static const int TIN  = 128;
static const int TOUT = 50;
static const int EPW  = 8;            // batch elements per warp
static const int WARPS = 8;           // warps per CTA
static const int EPB  = EPW * WARPS;  // 64 elements per CTA
static const int NTHREADS = 256;
static const int WP_ULL = 64 * 128;              // 8192 ull = 64KB permuted Whh
static const int HH_ULL = WARPS * EPW * 64;      // 4096 ull = 32KB duplicated h
static const int SMEM_BYTES = (WP_ULL + HH_ULL) * 8;

// ---------- f32x2 + fast-math primitives ----------
__device__ __forceinline__ ull pk2(float lo, float hi) {
    ull r; asm("mov.b64 %0,{%1,%2};" : "=l"(r) : "f"(lo), "f"(hi)); return r;
}
__device__ __forceinline__ void upk2(ull v, float& lo, float& hi) {
    asm("mov.b64 {%0,%1},%2;" : "=f"(lo), "=f"(hi) : "l"(v));
}
__device__ __forceinline__ ull fma2(ull a, ull b, ull c) {
    ull d; asm("fma.rn.f32x2 %0,%1,%2,%3;" : "=l"(d) : "l"(a), "l"(b), "l"(c)); return d;
}
__device__ __forceinline__ ull mul2(ull a, ull b) {
    ull d; asm("mul.rn.f32x2 %0,%1,%2;" : "=l"(d) : "l"(a), "l"(b)); return d;
}
__device__ __forceinline__ float ex2f(float x) {
    float r; asm("ex2.approx.f32 %0,%1;" : "=f"(r) : "f"(x)); return r;
}
__device__ __forceinline__ float rcpf(float x) {
    float r; asm("rcp.approx.f32 %0,%1;" : "=f"(r) : "f"(x)); return r;
}
__device__ __forceinline__ float sigf(float x) {
    // sigmoid(x) = 1/(1+2^(-x*log2e)); ex2 underflow/overflow both give correct limits
    return rcpf(1.0f + ex2f(-1.4426950408889634f * x));
}
__device__ __forceinline__ float tanhf_fast(float x) {
    x = fminf(15.0f, fmaxf(-15.0f, x));          // avoid ex2 overflow -> NaN
    float e = ex2f(-2.8853900817779268f * x);    // e = exp(-2x)
    return (1.0f - e) * rcpf(1.0f + e);
}
__device__ __forceinline__ ull sig2(ull v)  { float a, b; upk2(v, a, b); return pk2(sigf(a), sigf(b)); }
__device__ __forceinline__ ull tanh2(ull v) { float a, b; upk2(v, a, b); return pk2(tanhf_fast(a), tanhf_fast(b)); }

// ---------- recurrent GEMV core: acc[e][p] += h_e[k] * {W[nlo][k], W[nhi][k]} ----------
__device__ __forceinline__ void kloop(ull acc[EPW][4], const ull* __restrict__ Wp2,
                                      const ull* __restrict__ hh, int d0) {
#pragma unroll 2
    for (int k2 = 0; k2 < 32; k2++) {
        const ull* r = Wp2 + (k2 * 2) * 128 + d0;
        ull w00 = r[0],   w01 = r[32],  w02 = r[64],  w03 = r[96];    // k = 2*k2
        ull w10 = r[128], w11 = r[160], w12 = r[192], w13 = r[224];   // k = 2*k2+1
#pragma unroll
        for (int e = 0; e < EPW; e++) {
            ulonglong2 hv = *reinterpret_cast<const ulonglong2*>(hh + e * 64 + k2 * 2);
            acc[e][0] = fma2(hv.x, w00, acc[e][0]);
            acc[e][1] = fma2(hv.x, w01, acc[e][1]);
            acc[e][2] = fma2(hv.x, w02, acc[e][2]);
            acc[e][3] = fma2(hv.x, w03, acc[e][3]);
            acc[e][0] = fma2(hv.y, w10, acc[e][0]);
            acc[e][1] = fma2(hv.y, w11, acc[e][1]);
            acc[e][2] = fma2(hv.y, w12, acc[e][2]);
            acc[e][3] = fma2(hv.y, w13, acc[e][3]);
        }
    }
}

// ---------- LSTM pointwise + state update; writes duplicated h back to smem ----------
__device__ __forceinline__ void lstm_update(ull acc[EPW][4], ull c2[EPW], ull* hh, int d0,
                                            float hlo[EPW], float hhi[EPW]) {
    __syncwarp();   // all lanes done reading old h before anyone rewrites it
#pragma unroll
    for (int e = 0; e < EPW; e++) {
        ull iv = sig2(acc[e][0]);
        ull fv = sig2(acc[e][1]);
        ull gv = tanh2(acc[e][2]);
        ull ov = sig2(acc[e][3]);
        c2[e] = fma2(fv, c2[e], mul2(iv, gv));
        ull hv = mul2(ov, tanh2(c2[e]));
        float a, b; upk2(hv, a, b);
        hlo[e] = a; hhi[e] = b;
        hh[e * 64 + d0]      = pk2(a, a);   // duplicated for f32x2 A-operand
        hh[e * 64 + d0 + 32] = pk2(b, b);
    }
    __syncwarp();   // writes visible before next step's reads
}

__device__ __forceinline__ void load_consts(const float* __restrict__ Wih,
                                            const float* __restrict__ bih,
                                            const float* __restrict__ bhh,
                                            int d0, ull bias2[4], ull wi0[4], ull wi1[4]) {
#pragma unroll
    for (int p = 0; p < 4; p++) {
        int nlo = d0 + 64 * p, nhi = nlo + 32;
        bias2[p] = pk2(bih[nlo] + bhh[nlo], bih[nhi] + bhh[nhi]);
        wi0[p]   = pk2(Wih[2 * nlo],     Wih[2 * nhi]);
        wi1[p]   = pk2(Wih[2 * nlo + 1], Wih[2 * nhi + 1]);
    }
}

__global__ void __launch_bounds__(NTHREADS, 1)
lstm_seq2seq_kernel(const float* __restrict__ in,
                    const float* __restrict__ Wih_e, const float* __restrict__ Whh_e,
                    const float* __restrict__ bih_e, const float* __restrict__ bhh_e,
                    const float* __restrict__ Wih_d, const float* __restrict__ Whh_d,
                    const float* __restrict__ bih_d, const float* __restrict__ bhh_d,
                    const float* __restrict__ Wfc,   const float* __restrict__ bfc,
                    float* __restrict__ out, int B)
{
    extern __shared__ ull smem_u[];
    ull*   Wp2 = smem_u;                 // [64 k][4 p][32 d0] of {W[nlo][k],W[nhi][k]}
    float* WpF = (float*)Wp2;
    const int tid  = threadIdx.x;
    const int lane = tid & 31;
    const int wid  = tid >> 5;
    const int d0   = lane;
    ull* hh = smem_u + WP_ULL + wid * (EPW * 64);   // warp-private duplicated h
    const int base_b = blockIdx.x * EPB + wid * EPW;
    if (base_b >= B) return;
    const float* inb  = in  + (size_t)base_b * (TIN * 2);
    float*       outb = out + (size_t)base_b * (TOUT * 2);

    // ---- stage encoder Whh (pair-permuted) + zero h ----
    for (int idx = tid; idx < 256 * 64; idx += NTHREADS) {
        int n = idx >> 6, k = idx & 63;
        WpF[((k * 4 + (n >> 6)) * 32 + (n & 31)) * 2 + ((n >> 5) & 1)] = Whh_e[idx];
    }
    for (int idx = tid; idx < HH_ULL; idx += NTHREADS) smem_u[WP_ULL + idx] = 0ull;
    __syncthreads();

    ull bias2[4], wi0[4], wi1[4];
    load_consts(Wih_e, bih_e, bhh_e, d0, bias2, wi0, wi1);

    ull c2[EPW];
#pragma unroll
    for (int e = 0; e < EPW; e++) c2[e] = 0ull;
    float hlo[EPW], hhi[EPW];

    // ================= encoder: 128 steps =================
    for (int t = 0; t < TIN; t++) {
        ull acc[EPW][4];
#pragma unroll
        for (int e = 0; e < EPW; e++) {
            float2 xv = *reinterpret_cast<const float2*>(inb + e * (TIN * 2) + t * 2);
            ull x0d = pk2(xv.x, xv.x), x1d = pk2(xv.y, xv.y);
#pragma unroll
            for (int p = 0; p < 4; p++)
                acc[e][p] = fma2(x1d, wi1[p], fma2(x0d, wi0[p], bias2[p]));
        }
        kloop(acc, Wp2, hh, d0);
        lstm_update(acc, c2, hh, d0, hlo, hhi);
    }

    // ---- swap to decoder weights ----
    __syncthreads();
    for (int idx = tid; idx < 256 * 64; idx += NTHREADS) {
        int n = idx >> 6, k = idx & 63;
        WpF[((k * 4 + (n >> 6)) * 32 + (n & 31)) * 2 + ((n >> 5) & 1)] = Whh_d[idx];
    }
    load_consts(Wih_d, bih_d, bhh_d, d0, bias2, wi0, wi1);
    float wf0l = Wfc[d0], wf0h = Wfc[d0 + 32];
    float wf1l = Wfc[64 + d0], wf1h = Wfc[96 + d0];
    float bf0 = bfc[0], bf1 = bfc[1];
    __syncthreads();

    // decoder seed x = input_seq[:, -1]
    float x0[EPW], x1[EPW];
#pragma unroll
    for (int e = 0; e < EPW; e++) {
        float2 xv = *reinterpret_cast<const float2*>(inb + e * (TIN * 2) + (TIN - 1) * 2);
        x0[e] = xv.x; x1[e] = xv.y;
    }

    // ================= decoder: 50 steps =================
    for (int t = 0; t < TOUT; t++) {
        ull acc[EPW][4];
#pragma unroll
        for (int e = 0; e < EPW; e++) {
            ull x0d = pk2(x0[e], x0[e]), x1d = pk2(x1[e], x1[e]);
#pragma unroll
            for (int p = 0; p < 4; p++)
                acc[e][p] = fma2(x1d, wi1[p], fma2(x0d, wi0[p], bias2[p]));
        }
        kloop(acc, Wp2, hh, d0);
        lstm_update(acc, c2, hh, d0, hlo, hhi);

        // FC head: point = sigmoid(h @ Wfc^T + bfc); butterfly all-reduce over H
#pragma unroll
        for (int e = 0; e < EPW; e++) {
            float p0 = hlo[e] * wf0l + hhi[e] * wf0h;
            float p1 = hlo[e] * wf1l + hhi[e] * wf1h;
#pragma unroll
            for (int off = 16; off; off >>= 1) {
                p0 += __shfl_xor_sync(0xffffffffu, p0, off);
                p1 += __shfl_xor_sync(0xffffffffu, p1, off);
            }
            p0 = sigf(p0 + bf0);
            p1 = sigf(p1 + bf1);
            x0[e] = p0; x1[e] = p1;                // autoregressive feedback
            if (lane == e)
                *reinterpret_cast<float2*>(outb + e * (TOUT * 2) + t * 2) = make_float2(p0, p1);
        }
    }
}

extern "C" void kernel_launch(void* const* d_in, const int* in_sizes, int n_in,
                              void* d_out, int out_size) {
    const float* in    = (const float*)d_in[0];
    const float* Wih_e = (const float*)d_in[1];
    const float* Whh_e = (const float*)d_in[2];
    const float* bih_e = (const float*)d_in[3];
    const float* bhh_e = (const float*)d_in[4];
    const float* Wih_d = (const float*)d_in[5];
    const float* Whh_d = (const float*)d_in[6];
    const float* bih_d = (const float*)d_in[7];
    const float* bhh_d = (const float*)d_in[8];
    const float* Wfc   = (const float*)d_in[9];
    const float* bfc   = (const float*)d_in[10];
    float* out = (float*)d_out;

    int B = in_sizes[0] / (TIN * 2);          // 131072
    int grid = (B + EPB - 1) / EPB;           // 2048 CTAs

    cudaFuncSetAttribute(lstm_seq2seq_kernel,
                         cudaFuncAttributeMaxDynamicSharedMemorySize, SMEM_BYTES);
    lstm_seq2seq_kernel<<<grid, NTHREADS, SMEM_BYTES>>>(
        in, Wih_e, Whh_e, bih_e, bhh_e,
        Wih_d, Whh_d, bih_d, bhh_d, Wfc, bfc, out, B);
}

// round 6
// speedup vs baseline: 1.9965x; 1.9965x over previous
#include <cuda_runtime.h>
#include <cuda_bf16.h>
#include <cstdint>

typedef uint32_t u32;

#define TIN 128
#define TOUT 50
#define TSTEPS 178
#define NT 256
#define EPB 128                 // batch elements per CTA

#define STRIDE 132              // h-plane row stride (bytes), +4 pad kills bank conflicts
#define PL (128 * STRIDE)       // one h plane = 16896 B
#define SM_WFC 0                // 64 float2 = 512 B
#define SM_EXT 512              // 2 buffers x 128 rows x 16 B = 4096
#define SM_AH  4608             // 2 x PL  (h hi planes, double buffered)
#define SM_AL  (SM_AH + 2 * PL) // 2 x PL  (h lo planes)
#define SM_TOTAL (SM_AL + 2 * PL)   // 72192 B

#define L2E 1.4426950408889634f

// ---------- primitives ----------
__device__ __forceinline__ float ex2f(float x){ float r; asm("ex2.approx.f32 %0,%1;" : "=f"(r) : "f"(x)); return r; }
__device__ __forceinline__ float rcpf(float x){ float r; asm("rcp.approx.f32 %0,%1;" : "=f"(r) : "f"(x)); return r; }
__device__ __forceinline__ float sigf(float x){ return rcpf(1.0f + ex2f(-L2E * x)); }

__device__ __forceinline__ u32 pack_bf16(float a, float b){
    __nv_bfloat162 v = __floats2bfloat162_rn(a, b);
    return *reinterpret_cast<u32*>(&v);
}
__device__ __forceinline__ void split_hl(float v, float& hi, float& lo){
    hi = __bfloat162float(__float2bfloat16(v));
    lo = v - hi;
}

// mma.sync m16n8k16 bf16 (sm_80+ PTX, valid for generic sm_103 target)
__device__ __forceinline__ void mma16816(float d[4], const u32 a[4], const u32 b[2]){
    asm volatile(
        "mma.sync.aligned.m16n8k16.row.col.f32.bf16.bf16.f32 "
        "{%0,%1,%2,%3},{%4,%5,%6,%7},{%8,%9},{%0,%1,%2,%3};"
        : "+f"(d[0]), "+f"(d[1]), "+f"(d[2]), "+f"(d[3])
        : "r"(a[0]), "r"(a[1]), "r"(a[2]), "r"(a[3]), "r"(b[0]), "r"(b[1]));
}
__device__ __forceinline__ void mma1688(float d[4], const u32 a[2], u32 b){
    asm volatile(
        "mma.sync.aligned.m16n8k8.row.col.f32.bf16.bf16.f32 "
        "{%0,%1,%2,%3},{%4,%5},{%6},{%0,%1,%2,%3};"
        : "+f"(d[0]), "+f"(d[1]), "+f"(d[2]), "+f"(d[3])
        : "r"(a[0]), "r"(a[1]), "r"(b));
}

// ---------- per-thread weight registers ----------
// warp w owns hidden dims hd = 8w..8w+7; n-tiles nt=0..3 are gates i,f,g,o.
// thread's gate column n = nt*64 + w*8 + (lane/4).
struct Bregs { u32 bh[4][4][2]; u32 bl[4][4][2]; u32 be[4]; };

__device__ void load_B(Bregs& B, const float* __restrict__ Whh, const float* __restrict__ Wih,
                       const float* __restrict__ bih, const float* __restrict__ bhh,
                       int w, int g, int q){
#pragma unroll
    for (int nt = 0; nt < 4; nt++){
        const int n = nt * 64 + w * 8 + g;
        const float* row = Whh + n * 64;
#pragma unroll
        for (int kt = 0; kt < 4; kt++){
            const int k0 = kt * 16 + 2 * q;
            float h0,l0,h1,l1,h2,l2,h3,l3;
            split_hl(row[k0],     h0, l0);
            split_hl(row[k0 + 1], h1, l1);
            split_hl(row[k0 + 8], h2, l2);
            split_hl(row[k0 + 9], h3, l3);
            B.bh[kt][nt][0] = pack_bf16(h0, h1);
            B.bh[kt][nt][1] = pack_bf16(h2, h3);
            B.bl[kt][nt][0] = pack_bf16(l0, l1);
            B.bl[kt][nt][1] = pack_bf16(l2, l3);
        }
        // ext B rows: [W0h, W0l, W0h, W1h, W1l, W1h, bh, bl] (pairs with A_ext cols)
        float W0h,W0l,W1h,W1l,bsh,bsl;
        split_hl(Wih[n * 2],     W0h, W0l);
        split_hl(Wih[n * 2 + 1], W1h, W1l);
        split_hl(bih[n] + bhh[n], bsh, bsl);
        u32 be;
        if      (q == 0) be = pack_bf16(W0h, W0l);
        else if (q == 1) be = pack_bf16(W0h, W1h);
        else if (q == 2) be = pack_bf16(W1l, W1h);
        else             be = pack_bf16(bsh, bsl);
        B.be[nt] = be;
    }
}

// A_ext row m (16B): cols [x0h,x0h,x0l,x1h,x1h,x1l,1,1]
__device__ __forceinline__ void write_ext(char* e, int m, float x0, float x1){
    float x0h,x0l,x1h,x1l;
    split_hl(x0, x0h, x0l); split_hl(x1, x1h, x1l);
    uint4 v = make_uint4(pack_bf16(x0h, x0h), pack_bf16(x0l, x1h),
                         pack_bf16(x1h, x1l), pack_bf16(1.0f, 1.0f));
    *reinterpret_cast<uint4*>(e + m * 16) = v;
}

__device__ __forceinline__ void ldA(u32 a[4], const char* pl, int row, int kt, int q){
    const char* p = pl + row * STRIDE + kt * 32 + q * 4;
    a[0] = *(const u32*)p;
    a[1] = *(const u32*)(p + 8 * STRIDE);
    a[2] = *(const u32*)(p + 16);
    a[3] = *(const u32*)(p + 8 * STRIDE + 16);
}

__global__ void __launch_bounds__(NT, 1)
lstm_hmma_kernel(const float* __restrict__ in,
                 const float* __restrict__ Wih_e, const float* __restrict__ Whh_e,
                 const float* __restrict__ bih_e, const float* __restrict__ bhh_e,
                 const float* __restrict__ Wih_d, const float* __restrict__ Whh_d,
                 const float* __restrict__ bih_d, const float* __restrict__ bhh_d,
                 const float* __restrict__ Wfc,   const float* __restrict__ bfc,
                 float* __restrict__ out)
{
    extern __shared__ char smc[];
    const int tid = threadIdx.x;
    const int lane = tid & 31, w = tid >> 5;
    const int q = lane & 3, g = lane >> 2;
    const int base = blockIdx.x * EPB;
    float2* wfc = (float2*)(smc + SM_WFC);

    // ---- init smem ----
    if (tid < 64) wfc[tid] = make_float2(Wfc[tid], Wfc[64 + tid]);
    // zero all 4 h planes (buffer 0 = h0 = 0; buffer 1 overwritten before read)
    {
        u32* z = (u32*)(smc + SM_AH);
        for (int i = tid; i < 4 * PL / 4; i += NT) z[i] = 0u;
    }
    if (tid < EPB){
        float2 xv = *(const float2*)(in + (size_t)(base + tid) * (TIN * 2));
        write_ext(smc + SM_EXT, tid, xv.x, xv.y);
    }
    Bregs B;
    load_B(B, Whh_e, Wih_e, bih_e, bhh_e, w, g, q);
    float c[32];
#pragma unroll
    for (int i = 0; i < 32; i++) c[i] = 0.0f;
    const float bfc0 = bfc[0], bfc1 = bfc[1];
    __syncthreads();

    for (int t = 0; t < TSTEPS; t++){
        const int rb = t & 1, wbuf = rb ^ 1;
        const char* ah = smc + SM_AH + rb * PL;
        const char* al = smc + SM_AL + rb * PL;
        char* ahw = smc + SM_AH + wbuf * PL;
        char* alw = smc + SM_AL + wbuf * PL;
        const char* extr = smc + SM_EXT + rb * 2048;
        char* extw = smc + SM_EXT + wbuf * 2048;
        const bool dec = (t >= TIN);

#pragma unroll
        for (int mc = 0; mc < 2; mc++){
            float d[4][4][4];
#pragma unroll
            for (int mt = 0; mt < 4; mt++)
#pragma unroll
                for (int nt = 0; nt < 4; nt++)
#pragma unroll
                    for (int p = 0; p < 4; p++) d[mt][nt][p] = 0.0f;

#pragma unroll
            for (int kt = 0; kt < 4; kt++){
                u32 a[4][4];
#pragma unroll
                for (int mt = 0; mt < 4; mt++) ldA(a[mt], ah, (mc * 4 + mt) * 16 + g, kt, q);
#pragma unroll
                for (int mt = 0; mt < 4; mt++)
#pragma unroll
                    for (int nt = 0; nt < 4; nt++) mma16816(d[mt][nt], a[mt], B.bh[kt][nt]);
#pragma unroll
                for (int mt = 0; mt < 4; mt++)
#pragma unroll
                    for (int nt = 0; nt < 4; nt++) mma16816(d[mt][nt], a[mt], B.bl[kt][nt]);
#pragma unroll
                for (int mt = 0; mt < 4; mt++) ldA(a[mt], al, (mc * 4 + mt) * 16 + g, kt, q);
#pragma unroll
                for (int mt = 0; mt < 4; mt++)
#pragma unroll
                    for (int nt = 0; nt < 4; nt++) mma16816(d[mt][nt], a[mt], B.bh[kt][nt]);
            }
            // ext term: x@Wih + bias (K=8)
#pragma unroll
            for (int mt = 0; mt < 4; mt++){
                const int row = (mc * 4 + mt) * 16 + g;
                u32 ae[2];
                ae[0] = *(const u32*)(extr + row * 16 + q * 4);
                ae[1] = *(const u32*)(extr + (row + 8) * 16 + q * 4);
#pragma unroll
                for (int nt = 0; nt < 4; nt++) mma1688(d[mt][nt], ae, B.be[nt]);
            }

            // ---- epilogue: activations, c update, h split + STS ----
#pragma unroll
            for (int mt = 0; mt < 4; mt++){
                const int gm = mc * 4 + mt;
                float hv[4];
#pragma unroll
                for (int p = 0; p < 4; p++){
                    float ai = fminf(30.f, fmaxf(-30.f, d[mt][0][p]));
                    float af = fminf(30.f, fmaxf(-30.f, d[mt][1][p]));
                    float ag = fminf(15.f, fmaxf(-15.f, d[mt][2][p]));
                    float ao = fminf(30.f, fmaxf(-30.f, d[mt][3][p]));
                    // paired sigmoid(i), sigmoid(f): one rcp
                    float ei = ex2f(-L2E * ai), ef = ex2f(-L2E * af);
                    float pi = 1.f + ei, pf = 1.f + ef;
                    float r1 = rcpf(pi * pf);
                    float si = pf * r1, sf = pi * r1;
                    // paired sigmoid(o), tanh(g): one rcp
                    float eo = ex2f(-L2E * ao), eg = ex2f(-2.f * L2E * ag);
                    float po = 1.f + eo, pg = 1.f + eg;
                    float r2 = rcpf(po * pg);
                    float so = pg * r2;
                    float tg = (1.f - eg) * po * r2;
                    float cc = sf * c[gm * 4 + p] + si * tg;
                    c[gm * 4 + p] = cc;
                    float ccl = fminf(15.f, fmaxf(-15.f, cc));
                    float ec = ex2f(-2.f * L2E * ccl);
                    float tc = (1.f - ec) * rcpf(1.f + ec);
                    hv[p] = so * tc;
                }
                float h0h,h0l,h1h,h1l,h2h,h2l,h3h,h3l;
                split_hl(hv[0], h0h, h0l); split_hl(hv[1], h1h, h1l);
                split_hl(hv[2], h2h, h2l); split_hl(hv[3], h3h, h3l);
                const int col = w * 16 + q * 4;
                const int rA = gm * 16 + g, rB = rA + 8;
                *(u32*)(ahw + rA * STRIDE + col) = pack_bf16(h0h, h1h);
                *(u32*)(alw + rA * STRIDE + col) = pack_bf16(h0l, h1l);
                *(u32*)(ahw + rB * STRIDE + col) = pack_bf16(h2h, h3h);
                *(u32*)(alw + rB * STRIDE + col) = pack_bf16(h2l, h3l);
            }
        }

        if (!dec){
            if (tid < EPB){
                const int xi = (t + 1 < TIN) ? t + 1 : TIN - 1;   // t=127 rewrites x_127 = dec_in0
                float2 xv = *(const float2*)(in + (size_t)(base + tid) * (TIN * 2) + (size_t)xi * 2);
                write_ext(extw, tid, xv.x, xv.y);
            }
            __syncthreads();
            if (t == TIN - 1) load_B(B, Whh_d, Wih_d, bih_d, bhh_d, w, g, q);
        } else {
            __syncthreads();                        // h_t planes complete
            // FC head: 2 threads per element, 32 dims each
            const int m = tid >> 1, half = tid & 1;
            const char* hp = ahw + m * STRIDE + half * 64;
            const char* lp = alw + m * STRIDE + half * 64;
            float p0 = 0.f, p1 = 0.f;
#pragma unroll
            for (int j = 0; j < 16; j++){
                u32 hh = *(const u32*)(hp + j * 4), ll = *(const u32*)(lp + j * 4);
                __nv_bfloat162 hb = *reinterpret_cast<__nv_bfloat162*>(&hh);
                __nv_bfloat162 lb = *reinterpret_cast<__nv_bfloat162*>(&ll);
                float h0 = __bfloat162float(hb.x) + __bfloat162float(lb.x);
                float h1 = __bfloat162float(hb.y) + __bfloat162float(lb.y);
                const int k = half * 32 + j * 2;
                float2 wf0 = wfc[k], wf1 = wfc[k + 1];
                p0 += h0 * wf0.x + h1 * wf1.x;
                p1 += h0 * wf0.y + h1 * wf1.y;
            }
            p0 += __shfl_xor_sync(0xffffffffu, p0, 1);
            p1 += __shfl_xor_sync(0xffffffffu, p1, 1);
            if (half == 0){
                float s0 = sigf(p0 + bfc0);
                float s1 = sigf(p1 + bfc1);
                *(float2*)(out + (size_t)(base + m) * (TOUT * 2) + (size_t)(t - TIN) * 2)
                    = make_float2(s0, s1);
                if (t < TSTEPS - 1) write_ext(extw, m, s0, s1);   // autoregressive feedback
            }
            __syncthreads();
        }
    }
}

extern "C" void kernel_launch(void* const* d_in, const int* in_sizes, int n_in,
                              void* d_out, int out_size) {
    (void)n_in; (void)out_size;
    const float* in    = (const float*)d_in[0];
    const float* Wih_e = (const float*)d_in[1];
    const float* Whh_e = (const float*)d_in[2];
    const float* bih_e = (const float*)d_in[3];
    const float* bhh_e = (const float*)d_in[4];
    const float* Wih_d = (const float*)d_in[5];
    const float* Whh_d = (const float*)d_in[6];
    const float* bih_d = (const float*)d_in[7];
    const float* bhh_d = (const float*)d_in[8];
    const float* Wfc   = (const float*)d_in[9];
    const float* bfc   = (const float*)d_in[10];
    float* out = (float*)d_out;

    int B = in_sizes[0] / (TIN * 2);          // 131072
    int grid = B / EPB;                        // 1024 CTAs

    cudaFuncSetAttribute(lstm_hmma_kernel,
                         cudaFuncAttributeMaxDynamicSharedMemorySize, SM_TOTAL);
    lstm_hmma_kernel<<<grid, NT, SM_TOTAL>>>(
        in, Wih_e, Whh_e, bih_e, bhh_e,
        Wih_d, Whh_d, bih_d, bhh_d, Wfc, bfc, out);
}

// round 7
// speedup vs baseline: 4.3478x; 2.1777x over previous
#include <cuda_runtime.h>
#include <cuda_bf16.h>
#include <cstdint>

typedef uint32_t u32;

#define TIN 128
#define TOUT 50
#define TSTEPS 178
#define NT 256
#define EPB 128                 // batch elements per CTA

#define STRIDE 144              // h-plane row stride (bytes): 16B-aligned rows (ldmatrix), conflict-free
#define PL (128 * STRIDE)       // one h plane = 18432 B
#define SM_WFC 0                // 64 float2 = 512 B
#define SM_EXT 512              // 2 buffers x 128 rows x 16 B = 4096
#define SM_AH  4608             // 2 x PL (h bf16 planes, double buffered)
#define SM_TOTAL (SM_AH + 2 * PL)   // 41472 B

// ---------- primitives ----------
__device__ __forceinline__ float tanh_hw(float x){
    float r; asm("tanh.approx.f32 %0,%1;" : "=f"(r) : "f"(x)); return r;
}
__device__ __forceinline__ u32 smem_u32(const void* p){
    u32 a; asm("{.reg .u64 t; cvta.to.shared.u64 t, %1; cvt.u32.u64 %0, t;}" : "=r"(a) : "l"(p));
    return a;
}
__device__ __forceinline__ u32 pack_bf16(float a, float b){
    __nv_bfloat162 v = __floats2bfloat162_rn(a, b);
    return *reinterpret_cast<u32*>(&v);
}
__device__ __forceinline__ void split_hl(float v, float& hi, float& lo){
    hi = __bfloat162float(__float2bfloat16(v));
    lo = v - hi;
}

// mma.sync bf16 (sm_80+ PTX, valid for generic sm_103 target)
__device__ __forceinline__ void mma16816(float d[4], const u32 a[4], const u32 b[2]){
    asm volatile(
        "mma.sync.aligned.m16n8k16.row.col.f32.bf16.bf16.f32 "
        "{%0,%1,%2,%3},{%4,%5,%6,%7},{%8,%9},{%0,%1,%2,%3};"
        : "+f"(d[0]), "+f"(d[1]), "+f"(d[2]), "+f"(d[3])
        : "r"(a[0]), "r"(a[1]), "r"(a[2]), "r"(a[3]), "r"(b[0]), "r"(b[1]));
}
__device__ __forceinline__ void mma1688(float d[4], const u32 a[2], u32 b){
    asm volatile(
        "mma.sync.aligned.m16n8k8.row.col.f32.bf16.bf16.f32 "
        "{%0,%1,%2,%3},{%4,%5},{%6},{%0,%1,%2,%3};"
        : "+f"(d[0]), "+f"(d[1]), "+f"(d[2]), "+f"(d[3])
        : "r"(a[0]), "r"(a[1]), "r"(b));
}
// ldmatrix x4: one instruction loads a full 16x16 bf16 A fragment (sm_75+)
__device__ __forceinline__ void ldmA(u32 a[4], u32 addr){
    asm volatile("ldmatrix.sync.aligned.m8n8.x4.shared.b16 {%0,%1,%2,%3}, [%4];"
                 : "=r"(a[0]), "=r"(a[1]), "=r"(a[2]), "=r"(a[3]) : "r"(addr));
}

// ---------- per-thread weight registers ----------
// warp w owns hidden dims 8w..8w+7; thread (g=lane>>2,q=lane&3) owns gate col n = nt*64 + w*8 + g
// Whh split hi/lo (2-term: exact weights); rows for gates i,f,o (nt!=2) prescaled by 0.5 for tanh-sigmoid.
struct Bregs { u32 bh[4][4][2]; u32 bl[4][4][2]; u32 be[4]; };

__device__ void load_B(Bregs& B, const float* __restrict__ Whh, const float* __restrict__ Wih,
                       const float* __restrict__ bih, const float* __restrict__ bhh,
                       int w, int g, int q){
#pragma unroll
    for (int nt = 0; nt < 4; nt++){
        const float sc = (nt == 2) ? 1.0f : 0.5f;
        const int n = nt * 64 + w * 8 + g;
        const float* row = Whh + n * 64;
#pragma unroll
        for (int kt = 0; kt < 4; kt++){
            const int k0 = kt * 16 + 2 * q;
            float h0,l0,h1,l1,h2,l2,h3,l3;
            split_hl(row[k0]     * sc, h0, l0);
            split_hl(row[k0 + 1] * sc, h1, l1);
            split_hl(row[k0 + 8] * sc, h2, l2);
            split_hl(row[k0 + 9] * sc, h3, l3);
            B.bh[kt][nt][0] = pack_bf16(h0, h1);
            B.bh[kt][nt][1] = pack_bf16(h2, h3);
            B.bl[kt][nt][0] = pack_bf16(l0, l1);
            B.bl[kt][nt][1] = pack_bf16(l2, l3);
        }
        // ext B rows: [W0h, W0l, W0h, W1h, W1l, W1h, bh, bl] (pairs with A_ext cols)
        float W0h,W0l,W1h,W1l,bsh,bsl;
        split_hl(Wih[n * 2]     * sc, W0h, W0l);
        split_hl(Wih[n * 2 + 1] * sc, W1h, W1l);
        split_hl((bih[n] + bhh[n]) * sc, bsh, bsl);
        u32 be;
        if      (q == 0) be = pack_bf16(W0h, W0l);
        else if (q == 1) be = pack_bf16(W0h, W1h);
        else if (q == 2) be = pack_bf16(W1l, W1h);
        else             be = pack_bf16(bsh, bsl);
        B.be[nt] = be;
    }
}

// A_ext row m (16B): cols [x0h,x0h,x0l,x1h,x1h,x1l,1,1]
__device__ __forceinline__ void write_ext(char* e, int m, float x0, float x1){
    float x0h,x0l,x1h,x1l;
    split_hl(x0, x0h, x0l); split_hl(x1, x1h, x1l);
    uint4 v = make_uint4(pack_bf16(x0h, x0h), pack_bf16(x0l, x1h),
                         pack_bf16(x1h, x1l), pack_bf16(1.0f, 1.0f));
    *reinterpret_cast<uint4*>(e + m * 16) = v;
}

__global__ void __launch_bounds__(NT, 1)
lstm_hmma_kernel(const float* __restrict__ in,
                 const float* __restrict__ Wih_e, const float* __restrict__ Whh_e,
                 const float* __restrict__ bih_e, const float* __restrict__ bhh_e,
                 const float* __restrict__ Wih_d, const float* __restrict__ Whh_d,
                 const float* __restrict__ bih_d, const float* __restrict__ bhh_d,
                 const float* __restrict__ Wfc,   const float* __restrict__ bfc,
                 float* __restrict__ out)
{
    extern __shared__ char smc[];
    const int tid = threadIdx.x;
    const int lane = tid & 31, w = tid >> 5;
    const int q = lane & 3, g = lane >> 2;
    const int base = blockIdx.x * EPB;
    const u32 sb = smem_u32(smc);
    float2* wfc = (float2*)(smc + SM_WFC);

    // ldmatrix per-lane geometry: lanes 0-15 -> rows 0-15, lanes 16-31 -> same rows, +16B (k+8)
    const int lrow = lane & 15;
    const int lcol = (lane >> 4) * 16;

    // ---- init smem ----
    if (tid < 64) wfc[tid] = make_float2(Wfc[tid], Wfc[64 + tid]);
    {
        u32* z = (u32*)(smc + SM_AH);
        for (int i = tid; i < 2 * PL / 4; i += NT) z[i] = 0u;   // h0 = 0
    }
    if (tid < EPB){
        float2 xv = *(const float2*)(in + (size_t)(base + tid) * (TIN * 2));
        write_ext(smc + SM_EXT, tid, xv.x, xv.y);
    }
    Bregs B;
    load_B(B, Whh_e, Wih_e, bih_e, bhh_e, w, g, q);
    float c[32];
#pragma unroll
    for (int i = 0; i < 32; i++) c[i] = 0.0f;
    const float bfc0 = bfc[0], bfc1 = bfc[1];
    __syncthreads();

    for (int t = 0; t < TSTEPS; t++){
        const int rb = t & 1, wbuf = rb ^ 1;
        const u32 ah_u = sb + SM_AH + rb * PL;       // read plane (bf16 h)
        char* ahw = smc + SM_AH + wbuf * PL;          // write plane
        const char* extr = smc + SM_EXT + rb * 2048;
        char* extw = smc + SM_EXT + wbuf * 2048;
        const bool dec = (t >= TIN);

#pragma unroll
        for (int mc = 0; mc < 2; mc++){
            float d[4][4][4];
#pragma unroll
            for (int mt = 0; mt < 4; mt++)
#pragma unroll
                for (int nt = 0; nt < 4; nt++)
#pragma unroll
                    for (int p = 0; p < 4; p++) d[mt][nt][p] = 0.0f;

#pragma unroll
            for (int kt = 0; kt < 4; kt++){
                u32 a[4][4];
#pragma unroll
                for (int mt = 0; mt < 4; mt++){
                    const u32 addr = ah_u + (u32)(((mc * 4 + mt) * 16 + lrow) * STRIDE + kt * 32 + lcol);
                    ldmA(a[mt], addr);
                }
#pragma unroll
                for (int mt = 0; mt < 4; mt++)
#pragma unroll
                    for (int nt = 0; nt < 4; nt++) mma16816(d[mt][nt], a[mt], B.bh[kt][nt]);
#pragma unroll
                for (int mt = 0; mt < 4; mt++)
#pragma unroll
                    for (int nt = 0; nt < 4; nt++) mma16816(d[mt][nt], a[mt], B.bl[kt][nt]);
            }
            // ext term: x@Wih + bias (K=8)
#pragma unroll
            for (int mt = 0; mt < 4; mt++){
                const int row = (mc * 4 + mt) * 16 + g;
                u32 ae[2];
                ae[0] = *(const u32*)(extr + row * 16 + q * 4);
                ae[1] = *(const u32*)(extr + (row + 8) * 16 + q * 4);
#pragma unroll
                for (int nt = 0; nt < 4; nt++) mma1688(d[mt][nt], ae, B.be[nt]);
            }

            // ---- epilogue: HW-tanh activations (i,f,o prescaled by 0.5), c update, h STS ----
#pragma unroll
            for (int mt = 0; mt < 4; mt++){
                const int gm = mc * 4 + mt;
                float hv[4];
#pragma unroll
                for (int p = 0; p < 4; p++){
                    float si = fmaf(tanh_hw(d[mt][0][p]), 0.5f, 0.5f);
                    float sf = fmaf(tanh_hw(d[mt][1][p]), 0.5f, 0.5f);
                    float tg = tanh_hw(d[mt][2][p]);
                    float so = fmaf(tanh_hw(d[mt][3][p]), 0.5f, 0.5f);
                    float cc = sf * c[gm * 4 + p] + si * tg;
                    c[gm * 4 + p] = cc;
                    hv[p] = so * tanh_hw(cc);
                }
                const int col = w * 16 + q * 4;
                const int rA = gm * 16 + g, rB = rA + 8;
                *(u32*)(ahw + rA * STRIDE + col) = pack_bf16(hv[0], hv[1]);
                *(u32*)(ahw + rB * STRIDE + col) = pack_bf16(hv[2], hv[3]);
            }
        }

        if (!dec){
            if (tid < EPB){
                const int xi = (t + 1 < TIN) ? t + 1 : TIN - 1;   // t=127 rewrites x_127 = dec_in0
                float2 xv = *(const float2*)(in + (size_t)(base + tid) * (TIN * 2) + (size_t)xi * 2);
                write_ext(extw, tid, xv.x, xv.y);
            }
            __syncthreads();
            if (t == TIN - 1) load_B(B, Whh_d, Wih_d, bih_d, bhh_d, w, g, q);
        } else {
            __syncthreads();                        // h_t plane complete
            // FC head: 2 threads per element, 32 dims each
            const int m = tid >> 1, half = tid & 1;
            const char* hp = ahw + m * STRIDE + half * 64;
            float p0 = 0.f, p1 = 0.f;
#pragma unroll
            for (int j = 0; j < 16; j++){
                u32 hh = *(const u32*)(hp + j * 4);
                __nv_bfloat162 hb = *reinterpret_cast<__nv_bfloat162*>(&hh);
                float h0 = __bfloat162float(hb.x);
                float h1 = __bfloat162float(hb.y);
                const int k = half * 32 + j * 2;
                float2 wf0 = wfc[k], wf1 = wfc[k + 1];
                p0 += h0 * wf0.x + h1 * wf1.x;
                p1 += h0 * wf0.y + h1 * wf1.y;
            }
            p0 += __shfl_xor_sync(0xffffffffu, p0, 1);
            p1 += __shfl_xor_sync(0xffffffffu, p1, 1);
            if (half == 0){
                float s0 = fmaf(tanh_hw(0.5f * (p0 + bfc0)), 0.5f, 0.5f);
                float s1 = fmaf(tanh_hw(0.5f * (p1 + bfc1)), 0.5f, 0.5f);
                *(float2*)(out + (size_t)(base + m) * (TOUT * 2) + (size_t)(t - TIN) * 2)
                    = make_float2(s0, s1);
                if (t < TSTEPS - 1) write_ext(extw, m, s0, s1);   // autoregressive feedback
            }
            __syncthreads();
        }
    }
}

extern "C" void kernel_launch(void* const* d_in, const int* in_sizes, int n_in,
                              void* d_out, int out_size) {
    (void)n_in; (void)out_size;
    const float* in    = (const float*)d_in[0];
    const float* Wih_e = (const float*)d_in[1];
    const float* Whh_e = (const float*)d_in[2];
    const float* bih_e = (const float*)d_in[3];
    const float* bhh_e = (const float*)d_in[4];
    const float* Wih_d = (const float*)d_in[5];
    const float* Whh_d = (const float*)d_in[6];
    const float* bih_d = (const float*)d_in[7];
    const float* bhh_d = (const float*)d_in[8];
    const float* Wfc   = (const float*)d_in[9];
    const float* bfc   = (const float*)d_in[10];
    float* out = (float*)d_out;

    int B = in_sizes[0] / (TIN * 2);          // 131072
    int grid = B / EPB;                        // 1024 CTAs

    cudaFuncSetAttribute(lstm_hmma_kernel,
                         cudaFuncAttributeMaxDynamicSharedMemorySize, SM_TOTAL);
    lstm_hmma_kernel<<<grid, NT, SM_TOTAL>>>(
        in, Wih_e, Whh_e, bih_e, bhh_e,
        Wih_d, Whh_d, bih_d, bhh_d, Wfc, bfc, out);
}

// round 8
// speedup vs baseline: 6.1894x; 1.4236x over previous
#include <cuda_runtime.h>
#include <cuda_fp16.h>
#include <cstdint>

typedef uint32_t u32;

#define TIN 128
#define TOUT 50
#define TSTEPS 178
#define NT 256
#define EPB 128                 // batch elements per CTA

#define STRIDE 144              // h-plane row stride (bytes): 16B-aligned rows (ldmatrix), conflict-free
#define PL (128 * STRIDE)       // one h plane = 18432 B
#define SM_WFC 0                // 64 float2 = 512 B
#define SM_EXT 512              // 2 buffers x 128 rows x 16 B = 4096
#define SM_AH  4608             // 2 x PL (h fp16 planes, double buffered)
#define SM_TOTAL (SM_AH + 2 * PL)   // 41472 B

// ---------- primitives ----------
__device__ __forceinline__ float tanh_hw(float x){
    float r; asm("tanh.approx.f32 %0,%1;" : "=f"(r) : "f"(x)); return r;
}
__device__ __forceinline__ u32 smem_u32(const void* p){
    u32 a; asm("{.reg .u64 t; cvta.to.shared.u64 t, %1; cvt.u32.u64 %0, t;}" : "=r"(a) : "l"(p));
    return a;
}
__device__ __forceinline__ u32 pack_f16(float a, float b){
    __half2 v = __floats2half2_rn(a, b);
    return *reinterpret_cast<u32*>(&v);
}
__device__ __forceinline__ void split_hl(float v, float& hi, float& lo){
    hi = __half2float(__float2half_rn(v));
    lo = v - hi;
}

// mma.sync f16 (sm_80+ PTX, generic sm_103 target). NON-volatile: pure register
// dataflow; lets the scheduler interleave chunk-1 MMAs with chunk-0 epilogue.
__device__ __forceinline__ void mma16816(float d[4], const u32 a[4], const u32 b[2]){
    asm("mma.sync.aligned.m16n8k16.row.col.f32.f16.f16.f32 "
        "{%0,%1,%2,%3},{%4,%5,%6,%7},{%8,%9},{%0,%1,%2,%3};"
        : "+f"(d[0]), "+f"(d[1]), "+f"(d[2]), "+f"(d[3])
        : "r"(a[0]), "r"(a[1]), "r"(a[2]), "r"(a[3]), "r"(b[0]), "r"(b[1]));
}
__device__ __forceinline__ void mma1688(float d[4], const u32 a[2], u32 b){
    asm("mma.sync.aligned.m16n8k8.row.col.f32.f16.f16.f32 "
        "{%0,%1,%2,%3},{%4,%5},{%6},{%0,%1,%2,%3};"
        : "+f"(d[0]), "+f"(d[1]), "+f"(d[2]), "+f"(d[3])
        : "r"(a[0]), "r"(a[1]), "r"(b));
}
// ldmatrix x4: one 16x16 f16 A fragment; volatile so it stays ordered after the barrier
__device__ __forceinline__ void ldmA(u32 a[4], u32 addr){
    asm volatile("ldmatrix.sync.aligned.m8n8.x4.shared.b16 {%0,%1,%2,%3}, [%4];"
                 : "=r"(a[0]), "=r"(a[1]), "=r"(a[2]), "=r"(a[3]) : "r"(addr));
}

// ---------- per-thread weight registers ----------
// warp w owns hidden dims 8w..8w+7; thread (g=lane>>2,q=lane&3): B col n = nt*64 + w*8 + g.
// Whh single-term fp16; gates i,f,o (nt!=2) prescaled by 0.5 for tanh-based sigmoid.
struct Bregs { u32 bh[4][4][2]; u32 be[4]; };

__device__ void load_B(Bregs& B, const float* __restrict__ Whh, const float* __restrict__ Wih,
                       const float* __restrict__ bih, const float* __restrict__ bhh,
                       int w, int g, int q){
#pragma unroll
    for (int nt = 0; nt < 4; nt++){
        const float sc = (nt == 2) ? 1.0f : 0.5f;
        const int n = nt * 64 + w * 8 + g;
        const float* row = Whh + n * 64;
#pragma unroll
        for (int kt = 0; kt < 4; kt++){
            const int k0 = kt * 16 + 2 * q;
            B.bh[kt][nt][0] = pack_f16(row[k0]     * sc, row[k0 + 1] * sc);
            B.bh[kt][nt][1] = pack_f16(row[k0 + 8] * sc, row[k0 + 9] * sc);
        }
        // ext B rows: [W0h, W0l, W0h, W1h, W1l, W1h, bh, bl] (pairs with A_ext cols) — keeps
        // x@Wih + bias near-exact (hi/lo split), costs nothing extra (one K=8 MMA).
        float W0h,W0l,W1h,W1l,bsh,bsl;
        split_hl(Wih[n * 2]     * sc, W0h, W0l);
        split_hl(Wih[n * 2 + 1] * sc, W1h, W1l);
        split_hl((bih[n] + bhh[n]) * sc, bsh, bsl);
        u32 be;
        if      (q == 0) be = pack_f16(W0h, W0l);
        else if (q == 1) be = pack_f16(W0h, W1h);
        else if (q == 2) be = pack_f16(W1l, W1h);
        else             be = pack_f16(bsh, bsl);
        B.be[nt] = be;
    }
}

// A_ext row m (16B): cols [x0h,x0h,x0l,x1h,x1h,x1l,1,1]
__device__ __forceinline__ void write_ext(char* e, int m, float x0, float x1){
    float x0h,x0l,x1h,x1l;
    split_hl(x0, x0h, x0l); split_hl(x1, x1h, x1l);
    uint4 v = make_uint4(pack_f16(x0h, x0h), pack_f16(x0l, x1h),
                         pack_f16(x1h, x1l), pack_f16(1.0f, 1.0f));
    *reinterpret_cast<uint4*>(e + m * 16) = v;
}

__global__ void __launch_bounds__(NT, 1)
lstm_hmma_kernel(const float* __restrict__ in,
                 const float* __restrict__ Wih_e, const float* __restrict__ Whh_e,
                 const float* __restrict__ bih_e, const float* __restrict__ bhh_e,
                 const float* __restrict__ Wih_d, const float* __restrict__ Whh_d,
                 const float* __restrict__ bih_d, const float* __restrict__ bhh_d,
                 const float* __restrict__ Wfc,   const float* __restrict__ bfc,
                 float* __restrict__ out)
{
    extern __shared__ char smc[];
    const int tid = threadIdx.x;
    const int lane = tid & 31, w = tid >> 5;
    const int q = lane & 3, g = lane >> 2;
    const int base = blockIdx.x * EPB;
    const u32 sb = smem_u32(smc);
    float2* wfc = (float2*)(smc + SM_WFC);

    // ldmatrix geometry: lanes 0-15 -> rows, lanes 16-31 -> same rows +16B (k+8)
    const int lrow = lane & 15;
    const int lcol = (lane >> 4) * 16;

    // ---- init smem ----
    if (tid < 64) wfc[tid] = make_float2(Wfc[tid], Wfc[64 + tid]);
    {
        u32* z = (u32*)(smc + SM_AH);
        for (int i = tid; i < 2 * PL / 4; i += NT) z[i] = 0u;   // h0 = 0
    }
    if (tid < EPB){
        float2 xv = *(const float2*)(in + (size_t)(base + tid) * (TIN * 2));
        write_ext(smc + SM_EXT, tid, xv.x, xv.y);
    }
    Bregs B;
    load_B(B, Whh_e, Wih_e, bih_e, bhh_e, w, g, q);
    float c[32];
#pragma unroll
    for (int i = 0; i < 32; i++) c[i] = 0.0f;
    const float bfc0 = bfc[0], bfc1 = bfc[1];
    __syncthreads();

    for (int t = 0; t < TSTEPS; t++){
        const int rb = t & 1, wbuf = rb ^ 1;
        const u32 ah_u = sb + SM_AH + rb * PL;       // read plane (fp16 h)
        char* ahw = smc + SM_AH + wbuf * PL;          // write plane
        const char* extr = smc + SM_EXT + rb * 2048;
        char* extw = smc + SM_EXT + wbuf * 2048;
        const bool dec = (t >= TIN);

#pragma unroll
        for (int mc = 0; mc < 2; mc++){
            float d[4][4][4];
#pragma unroll
            for (int mt = 0; mt < 4; mt++)
#pragma unroll
                for (int nt = 0; nt < 4; nt++)
#pragma unroll
                    for (int p = 0; p < 4; p++) d[mt][nt][p] = 0.0f;

#pragma unroll
            for (int kt = 0; kt < 4; kt++){
                u32 a[4][4];
#pragma unroll
                for (int mt = 0; mt < 4; mt++){
                    const u32 addr = ah_u + (u32)(((mc * 4 + mt) * 16 + lrow) * STRIDE + kt * 32 + lcol);
                    ldmA(a[mt], addr);
                }
#pragma unroll
                for (int mt = 0; mt < 4; mt++)
#pragma unroll
                    for (int nt = 0; nt < 4; nt++) mma16816(d[mt][nt], a[mt], B.bh[kt][nt]);
            }
            // ext term: x@Wih + bias (K=8)
#pragma unroll
            for (int mt = 0; mt < 4; mt++){
                const int row = (mc * 4 + mt) * 16 + g;
                u32 ae[2];
                ae[0] = *(const u32*)(extr + row * 16 + q * 4);
                ae[1] = *(const u32*)(extr + (row + 8) * 16 + q * 4);
#pragma unroll
                for (int nt = 0; nt < 4; nt++) mma1688(d[mt][nt], ae, B.be[nt]);
            }

            // ---- epilogue: HW-tanh activations (i,f,o prescaled 0.5), c update, h STS ----
#pragma unroll
            for (int mt = 0; mt < 4; mt++){
                const int gm = mc * 4 + mt;
                float hv[4];
#pragma unroll
                for (int p = 0; p < 4; p++){
                    float si = fmaf(tanh_hw(d[mt][0][p]), 0.5f, 0.5f);
                    float sf = fmaf(tanh_hw(d[mt][1][p]), 0.5f, 0.5f);
                    float tg = tanh_hw(d[mt][2][p]);
                    float so = fmaf(tanh_hw(d[mt][3][p]), 0.5f, 0.5f);
                    float cc = sf * c[gm * 4 + p] + si * tg;
                    c[gm * 4 + p] = cc;
                    hv[p] = so * tanh_hw(cc);
                }
                const int col = w * 16 + q * 4;
                const int rA = gm * 16 + g, rB = rA + 8;
                *(u32*)(ahw + rA * STRIDE + col) = pack_f16(hv[0], hv[1]);
                *(u32*)(ahw + rB * STRIDE + col) = pack_f16(hv[2], hv[3]);
            }
        }

        if (!dec){
            if (tid < EPB){
                const int xi = (t + 1 < TIN) ? t + 1 : TIN - 1;   // t=127 rewrites x_127 = dec_in0
                float2 xv = *(const float2*)(in + (size_t)(base + tid) * (TIN * 2) + (size_t)xi * 2);
                write_ext(extw, tid, xv.x, xv.y);
            }
            __syncthreads();
            if (t == TIN - 1) load_B(B, Whh_d, Wih_d, bih_d, bhh_d, w, g, q);
        } else {
            __syncthreads();                        // h_t plane complete
            // FC head: 2 threads per element, 32 dims each
            const int m = tid >> 1, half = tid & 1;
            const char* hp = ahw + m * STRIDE + half * 64;
            float p0 = 0.f, p1 = 0.f;
#pragma unroll
            for (int j = 0; j < 16; j++){
                u32 hh = *(const u32*)(hp + j * 4);
                __half2 hb = *reinterpret_cast<__half2*>(&hh);
                float h0 = __half2float(hb.x);
                float h1 = __half2float(hb.y);
                const int k = half * 32 + j * 2;
                float2 wf0 = wfc[k], wf1 = wfc[k + 1];
                p0 += h0 * wf0.x + h1 * wf1.x;
                p1 += h0 * wf0.y + h1 * wf1.y;
            }
            p0 += __shfl_xor_sync(0xffffffffu, p0, 1);
            p1 += __shfl_xor_sync(0xffffffffu, p1, 1);
            if (half == 0){
                float s0 = fmaf(tanh_hw(0.5f * (p0 + bfc0)), 0.5f, 0.5f);
                float s1 = fmaf(tanh_hw(0.5f * (p1 + bfc1)), 0.5f, 0.5f);
                *(float2*)(out + (size_t)(base + m) * (TOUT * 2) + (size_t)(t - TIN) * 2)
                    = make_float2(s0, s1);
                if (t < TSTEPS - 1) write_ext(extw, m, s0, s1);   // autoregressive feedback
            }
            __syncthreads();
        }
    }
}

extern "C" void kernel_launch(void* const* d_in, const int* in_sizes, int n_in,
                              void* d_out, int out_size) {
    (void)n_in; (void)out_size;
    const float* in    = (const float*)d_in[0];
    const float* Wih_e = (const float*)d_in[1];
    const float* Whh_e = (const float*)d_in[2];
    const float* bih_e = (const float*)d_in[3];
    const float* bhh_e = (const float*)d_in[4];
    const float* Wih_d = (const float*)d_in[5];
    const float* Whh_d = (const float*)d_in[6];
    const float* bih_d = (const float*)d_in[7];
    const float* bhh_d = (const float*)d_in[8];
    const float* Wfc   = (const float*)d_in[9];
    const float* bfc   = (const float*)d_in[10];
    float* out = (float*)d_out;

    int B = in_sizes[0] / (TIN * 2);          // 131072
    int grid = B / EPB;                        // 1024 CTAs

    cudaFuncSetAttribute(lstm_hmma_kernel,
                         cudaFuncAttributeMaxDynamicSharedMemorySize, SM_TOTAL);
    lstm_hmma_kernel<<<grid, NT, SM_TOTAL>>>(
        in, Wih_e, Whh_e, bih_e, bhh_e,
        Wih_d, Whh_d, bih_d, bhh_d, Wfc, bfc, out);
}

// round 9
// speedup vs baseline: 6.7934x; 1.0976x over previous
#include <cuda_runtime.h>
#include <cuda_fp16.h>
#include <cstdint>

typedef uint32_t u32;

#define TIN 128
#define TOUT 50
#define TSTEPS 178
#define NT 256
#define EPB 128                 // batch elements per CTA

#define STRIDE 144              // h-plane row stride (bytes): 16B-aligned rows (ldmatrix), conflict-free
#define PL (128 * STRIDE)       // one h plane = 18432 B
#define SM_WFC 0                // 64 float2 = 512 B
#define SM_EXT 512              // 2 buffers x 128 rows x 16 B = 4096
#define SM_AH  4608             // 2 x PL (h fp16 planes, double buffered)
#define SM_TOTAL (SM_AH + 2 * PL)   // 41472 B

// ---------- primitives ----------
__device__ __forceinline__ float tanh_hw(float x){
    float r; asm("tanh.approx.f32 %0,%1;" : "=f"(r) : "f"(x)); return r;
}
__device__ __forceinline__ u32 tanh2u(u32 x){           // two tanh in one MUFU op
    u32 r; asm("tanh.approx.f16x2 %0,%1;" : "=r"(r) : "r"(x)); return r;
}
__device__ __forceinline__ u32 smem_u32(const void* p){
    u32 a; asm("{.reg .u64 t; cvta.to.shared.u64 t, %1; cvt.u32.u64 %0, t;}" : "=r"(a) : "l"(p));
    return a;
}
__device__ __forceinline__ u32 pack_f16(float a, float b){
    __half2 v = __floats2half2_rn(a, b);
    return *reinterpret_cast<u32*>(&v);
}
__device__ __forceinline__ __half2 u2h(u32 x){ return *reinterpret_cast<__half2*>(&x); }
__device__ __forceinline__ u32 h2u(__half2 x){ return *reinterpret_cast<u32*>(&x); }
__device__ __forceinline__ void split_hl(float v, float& hi, float& lo){
    hi = __half2float(__float2half_rn(v));
    lo = v - hi;
}

// mma.sync f16 (sm_80+ PTX, generic sm_103 target); non-volatile register dataflow
__device__ __forceinline__ void mma16816(float d[4], const u32 a[4], const u32 b[2]){
    asm("mma.sync.aligned.m16n8k16.row.col.f32.f16.f16.f32 "
        "{%0,%1,%2,%3},{%4,%5,%6,%7},{%8,%9},{%0,%1,%2,%3};"
        : "+f"(d[0]), "+f"(d[1]), "+f"(d[2]), "+f"(d[3])
        : "r"(a[0]), "r"(a[1]), "r"(a[2]), "r"(a[3]), "r"(b[0]), "r"(b[1]));
}
__device__ __forceinline__ void mma1688(float d[4], const u32 a[2], u32 b){
    asm("mma.sync.aligned.m16n8k8.row.col.f32.f16.f16.f32 "
        "{%0,%1,%2,%3},{%4,%5},{%6},{%0,%1,%2,%3};"
        : "+f"(d[0]), "+f"(d[1]), "+f"(d[2]), "+f"(d[3])
        : "r"(a[0]), "r"(a[1]), "r"(b));
}
__device__ __forceinline__ void ldmA(u32 a[4], u32 addr){
    asm volatile("ldmatrix.sync.aligned.m8n8.x4.shared.b16 {%0,%1,%2,%3}, [%4];"
                 : "=r"(a[0]), "=r"(a[1]), "=r"(a[2]), "=r"(a[3]) : "r"(addr));
}

// ---------- per-thread weight registers ----------
// warp w owns hidden dims 8w..8w+7; thread (g=lane>>2,q=lane&3): B col n = nt*64 + w*8 + g.
// fp16 single-term Whh; gates i,f,o (nt!=2) prescaled by 0.5 for tanh-based sigmoid.
struct Bregs { u32 bh[4][4][2]; u32 be[4]; };

__device__ void load_B(Bregs& B, const float* __restrict__ Whh, const float* __restrict__ Wih,
                       const float* __restrict__ bih, const float* __restrict__ bhh,
                       int w, int g, int q){
#pragma unroll
    for (int nt = 0; nt < 4; nt++){
        const float sc = (nt == 2) ? 1.0f : 0.5f;
        const int n = nt * 64 + w * 8 + g;
        const float* row = Whh + n * 64;
#pragma unroll
        for (int kt = 0; kt < 4; kt++){
            const int k0 = kt * 16 + 2 * q;
            B.bh[kt][nt][0] = pack_f16(row[k0]     * sc, row[k0 + 1] * sc);
            B.bh[kt][nt][1] = pack_f16(row[k0 + 8] * sc, row[k0 + 9] * sc);
        }
        // ext B rows: [W0h, W0l, W0h, W1h, W1l, W1h, bh, bl] (pairs with A_ext cols)
        float W0h,W0l,W1h,W1l,bsh,bsl;
        split_hl(Wih[n * 2]     * sc, W0h, W0l);
        split_hl(Wih[n * 2 + 1] * sc, W1h, W1l);
        split_hl((bih[n] + bhh[n]) * sc, bsh, bsl);
        u32 be;
        if      (q == 0) be = pack_f16(W0h, W0l);
        else if (q == 1) be = pack_f16(W0h, W1h);
        else if (q == 2) be = pack_f16(W1l, W1h);
        else             be = pack_f16(bsh, bsl);
        B.be[nt] = be;
    }
}

// A_ext row m (16B): cols [x0h,x0h,x0l,x1h,x1h,x1l,1,1]
__device__ __forceinline__ void write_ext(char* e, int m, float x0, float x1){
    float x0h,x0l,x1h,x1l;
    split_hl(x0, x0h, x0l); split_hl(x1, x1h, x1l);
    uint4 v = make_uint4(pack_f16(x0h, x0h), pack_f16(x0l, x1h),
                         pack_f16(x1h, x1l), pack_f16(1.0f, 1.0f));
    *reinterpret_cast<uint4*>(e + m * 16) = v;
}

// ---- one 16-row m-tile: gates GEMM + ext term ----
__device__ __forceinline__ void mma_tile(float d[4][4], u32 ah_u, const char* extr,
                                         const Bregs& B, int mt8, int lrow, int lcol,
                                         int g, int q){
#pragma unroll
    for (int nt = 0; nt < 4; nt++)
#pragma unroll
        for (int p = 0; p < 4; p++) d[nt][p] = 0.0f;
#pragma unroll
    for (int kt = 0; kt < 4; kt++){
        u32 a[4];
        ldmA(a, ah_u + (u32)((mt8 * 16 + lrow) * STRIDE + kt * 32 + lcol));
#pragma unroll
        for (int nt = 0; nt < 4; nt++) mma16816(d[nt], a, B.bh[kt][nt]);
    }
    const int row = mt8 * 16 + g;
    u32 ae[2];
    ae[0] = *(const u32*)(extr + row * 16 + q * 4);
    ae[1] = *(const u32*)(extr + (row + 8) * 16 + q * 4);
#pragma unroll
    for (int nt = 0; nt < 4; nt++) mma1688(d[nt], ae, B.be[nt]);
}

// ---- deferred epilogue for one m-tile: f16x2 activations, fp32 c, packed h STS ----
__device__ __forceinline__ void epi_tile(const float d[4][4], float* c4,
                                         char* ahw, int rowA, int col){
    const __half2 H05 = __floats2half2_rn(0.5f, 0.5f);
#pragma unroll
    for (int pr = 0; pr < 2; pr++){
        const int p0 = pr * 2, p1 = p0 + 1;
        u32 ti = tanh2u(pack_f16(d[0][p0], d[0][p1]));
        u32 tf = tanh2u(pack_f16(d[1][p0], d[1][p1]));
        u32 tg = tanh2u(pack_f16(d[2][p0], d[2][p1]));
        u32 to = tanh2u(pack_f16(d[3][p0], d[3][p1]));
        __half2 si = __hfma2(u2h(ti), H05, H05);
        __half2 sf = __hfma2(u2h(tf), H05, H05);
        __half2 so = __hfma2(u2h(to), H05, H05);
        float2 sif = __half22float2(si);
        float2 sff = __half22float2(sf);
        float2 tgf = __half22float2(u2h(tg));
        float c0 = fmaf(sff.x, c4[p0], sif.x * tgf.x);
        float c1 = fmaf(sff.y, c4[p1], sif.y * tgf.y);
        c4[p0] = c0; c4[p1] = c1;
        u32 tc = tanh2u(pack_f16(c0, c1));
        __half2 hv = __hmul2(so, u2h(tc));      // already-packed h pair
        *(u32*)(ahw + (rowA + pr * 8) * STRIDE + col) = h2u(hv);
    }
}

__global__ void __launch_bounds__(NT, 1)
lstm_hmma_kernel(const float* __restrict__ in,
                 const float* __restrict__ Wih_e, const float* __restrict__ Whh_e,
                 const float* __restrict__ bih_e, const float* __restrict__ bhh_e,
                 const float* __restrict__ Wih_d, const float* __restrict__ Whh_d,
                 const float* __restrict__ bih_d, const float* __restrict__ bhh_d,
                 const float* __restrict__ Wfc,   const float* __restrict__ bfc,
                 float* __restrict__ out)
{
    extern __shared__ char smc[];
    const int tid = threadIdx.x;
    const int lane = tid & 31, w = tid >> 5;
    const int q = lane & 3, g = lane >> 2;
    const int base = blockIdx.x * EPB;
    const u32 sb = smem_u32(smc);
    float2* wfc = (float2*)(smc + SM_WFC);

    const int lrow = lane & 15;
    const int lcol = (lane >> 4) * 16;
    const int col  = w * 16 + q * 4;

    // ---- init smem ----
    if (tid < 64) wfc[tid] = make_float2(Wfc[tid], Wfc[64 + tid]);
    {
        u32* z = (u32*)(smc + SM_AH);
        for (int i = tid; i < 2 * PL / 4; i += NT) z[i] = 0u;   // h0 = 0
    }
    if (tid < EPB){
        float2 xv = *(const float2*)(in + (size_t)(base + tid) * (TIN * 2));
        write_ext(smc + SM_EXT, tid, xv.x, xv.y);
    }
    Bregs B;
    load_B(B, Whh_e, Wih_e, bih_e, bhh_e, w, g, q);
    float c[32];
#pragma unroll
    for (int i = 0; i < 32; i++) c[i] = 0.0f;
    const float bfc0 = bfc[0], bfc1 = bfc[1];
    __syncthreads();

    for (int t = 0; t < TSTEPS; t++){
        const int rb = t & 1, wbuf = rb ^ 1;
        const u32 ah_u = sb + SM_AH + rb * PL;       // read plane (fp16 h)
        char* ahw = smc + SM_AH + wbuf * PL;          // write plane
        const char* extr = smc + SM_EXT + rb * 2048;
        char* extw = smc + SM_EXT + wbuf * 2048;
        const bool dec = (t >= TIN);

        // ---- software-pipelined 8 m-tiles: MMA(i) overlaps epilogue(i-1) ----
        float d[2][4][4];
        mma_tile(d[0], ah_u, extr, B, 0, lrow, lcol, g, q);
#pragma unroll
        for (int mt8 = 1; mt8 < 8; mt8++){
            mma_tile(d[mt8 & 1], ah_u, extr, B, mt8, lrow, lcol, g, q);
            epi_tile(d[(mt8 - 1) & 1], c + (mt8 - 1) * 4, ahw, (mt8 - 1) * 16 + g, col);
        }
        epi_tile(d[1], c + 28, ahw, 7 * 16 + g, col);

        if (!dec){
            if (tid < EPB){
                const int xi = (t + 1 < TIN) ? t + 1 : TIN - 1;   // t=127 rewrites x_127 = dec_in0
                float2 xv = *(const float2*)(in + (size_t)(base + tid) * (TIN * 2) + (size_t)xi * 2);
                write_ext(extw, tid, xv.x, xv.y);
            }
            __syncthreads();
            if (t == TIN - 1) load_B(B, Whh_d, Wih_d, bih_d, bhh_d, w, g, q);
        } else {
            __syncthreads();                        // h_t plane complete
            // FC head: 2 threads per element, 32 dims each
            const int m = tid >> 1, half = tid & 1;
            const char* hp = ahw + m * STRIDE + half * 64;
            float p0 = 0.f, p1 = 0.f;
#pragma unroll
            for (int j = 0; j < 16; j++){
                u32 hh = *(const u32*)(hp + j * 4);
                __half2 hb = u2h(hh);
                float h0 = __half2float(hb.x);
                float h1 = __half2float(hb.y);
                const int k = half * 32 + j * 2;
                float2 wf0 = wfc[k], wf1 = wfc[k + 1];
                p0 += h0 * wf0.x + h1 * wf1.x;
                p1 += h0 * wf0.y + h1 * wf1.y;
            }
            p0 += __shfl_xor_sync(0xffffffffu, p0, 1);
            p1 += __shfl_xor_sync(0xffffffffu, p1, 1);
            if (half == 0){
                float s0 = fmaf(tanh_hw(0.5f * (p0 + bfc0)), 0.5f, 0.5f);
                float s1 = fmaf(tanh_hw(0.5f * (p1 + bfc1)), 0.5f, 0.5f);
                *(float2*)(out + (size_t)(base + m) * (TOUT * 2) + (size_t)(t - TIN) * 2)
                    = make_float2(s0, s1);
                if (t < TSTEPS - 1) write_ext(extw, m, s0, s1);   // autoregressive feedback
            }
            __syncthreads();
        }
    }
}

extern "C" void kernel_launch(void* const* d_in, const int* in_sizes, int n_in,
                              void* d_out, int out_size) {
    (void)n_in; (void)out_size;
    const float* in    = (const float*)d_in[0];
    const float* Wih_e = (const float*)d_in[1];
    const float* Whh_e = (const float*)d_in[2];
    const float* bih_e = (const float*)d_in[3];
    const float* bhh_e = (const float*)d_in[4];
    const float* Wih_d = (const float*)d_in[5];
    const float* Whh_d = (const float*)d_in[6];
    const float* bih_d = (const float*)d_in[7];
    const float* bhh_d = (const float*)d_in[8];
    const float* Wfc   = (const float*)d_in[9];
    const float* bfc   = (const float*)d_in[10];
    float* out = (float*)d_out;

    int B = in_sizes[0] / (TIN * 2);          // 131072
    int grid = B / EPB;                        // 1024 CTAs

    cudaFuncSetAttribute(lstm_hmma_kernel,
                         cudaFuncAttributeMaxDynamicSharedMemorySize, SM_TOTAL);
    lstm_hmma_kernel<<<grid, NT, SM_TOTAL>>>(
        in, Wih_e, Whh_e, bih_e, bhh_e,
        Wih_d, Whh_d, bih_d, bhh_d, Wfc, bfc, out);
}

// round 10
// speedup vs baseline: 8.1277x; 1.1964x over previous
#include <cuda_runtime.h>
#include <cuda_fp16.h>
#include <cstdint>

typedef uint32_t u32;

#define TIN 128
#define TOUT 50
#define TSTEPS 178
#define NT 256
#define EPB 128                 // batch elements per CTA

#define STRIDE 144              // h-plane row stride (bytes): 16B-aligned rows (ldmatrix), conflict-free
#define PL (128 * STRIDE)       // one h plane = 18432 B
#define SM_WFC 0                // 64 float2 = 512 B
#define SM_EXT 512              // 2 buffers x 128 rows x 16 B = 4096
#define SM_AH  4608             // 2 x PL (h fp16 planes, double buffered)
#define SM_TOTAL (SM_AH + 2 * PL)   // 41472 B  (x2 CTAs = 83 KB/SM, fits)

// ---------- primitives ----------
__device__ __forceinline__ float tanh_hw(float x){
    float r; asm("tanh.approx.f32 %0,%1;" : "=f"(r) : "f"(x)); return r;
}
__device__ __forceinline__ u32 tanh2u(u32 x){           // two tanh in one MUFU op
    u32 r; asm("tanh.approx.f16x2 %0,%1;" : "=r"(r) : "r"(x)); return r;
}
__device__ __forceinline__ u32 smem_u32(const void* p){
    u32 a; asm("{.reg .u64 t; cvta.to.shared.u64 t, %1; cvt.u32.u64 %0, t;}" : "=r"(a) : "l"(p));
    return a;
}
__device__ __forceinline__ u32 pack_f16(float a, float b){
    __half2 v = __floats2half2_rn(a, b);
    return *reinterpret_cast<u32*>(&v);
}
__device__ __forceinline__ __half2 u2h(u32 x){ return *reinterpret_cast<__half2*>(&x); }
__device__ __forceinline__ u32 h2u(__half2 x){ return *reinterpret_cast<u32*>(&x); }
__device__ __forceinline__ void split_hl(float v, float& hi, float& lo){
    hi = __half2float(__float2half_rn(v));
    lo = v - hi;
}

// mma.sync f16 (sm_80+ PTX, generic sm_103 target); non-volatile register dataflow
__device__ __forceinline__ void mma16816(float d[4], const u32 a[4], const u32 b[2]){
    asm("mma.sync.aligned.m16n8k16.row.col.f32.f16.f16.f32 "
        "{%0,%1,%2,%3},{%4,%5,%6,%7},{%8,%9},{%0,%1,%2,%3};"
        : "+f"(d[0]), "+f"(d[1]), "+f"(d[2]), "+f"(d[3])
        : "r"(a[0]), "r"(a[1]), "r"(a[2]), "r"(a[3]), "r"(b[0]), "r"(b[1]));
}
__device__ __forceinline__ void mma1688(float d[4], const u32 a[2], u32 b){
    asm("mma.sync.aligned.m16n8k8.row.col.f32.f16.f16.f32 "
        "{%0,%1,%2,%3},{%4,%5},{%6},{%0,%1,%2,%3};"
        : "+f"(d[0]), "+f"(d[1]), "+f"(d[2]), "+f"(d[3])
        : "r"(a[0]), "r"(a[1]), "r"(b));
}
__device__ __forceinline__ void ldmA(u32 a[4], u32 addr){
    asm volatile("ldmatrix.sync.aligned.m8n8.x4.shared.b16 {%0,%1,%2,%3}, [%4];"
                 : "=r"(a[0]), "=r"(a[1]), "=r"(a[2]), "=r"(a[3]) : "r"(addr));
}

// ---------- per-thread weight registers ----------
// warp w owns hidden dims 8w..8w+7; thread (g=lane>>2,q=lane&3): B col n = nt*64 + w*8 + g.
// fp16 single-term Whh; gates i,f,o (nt!=2) prescaled by 0.5 for tanh-based sigmoid.
struct Bregs { u32 bh[4][4][2]; u32 be[4]; };

__device__ void load_B(Bregs& B, const float* __restrict__ Whh, const float* __restrict__ Wih,
                       const float* __restrict__ bih, const float* __restrict__ bhh,
                       int w, int g, int q){
#pragma unroll
    for (int nt = 0; nt < 4; nt++){
        const float sc = (nt == 2) ? 1.0f : 0.5f;
        const int n = nt * 64 + w * 8 + g;
        const float* row = Whh + n * 64;
#pragma unroll
        for (int kt = 0; kt < 4; kt++){
            const int k0 = kt * 16 + 2 * q;
            B.bh[kt][nt][0] = pack_f16(row[k0]     * sc, row[k0 + 1] * sc);
            B.bh[kt][nt][1] = pack_f16(row[k0 + 8] * sc, row[k0 + 9] * sc);
        }
        // ext B rows: [W0h, W0l, W0h, W1h, W1l, W1h, bh, bl] (pairs with A_ext cols)
        float W0h,W0l,W1h,W1l,bsh,bsl;
        split_hl(Wih[n * 2]     * sc, W0h, W0l);
        split_hl(Wih[n * 2 + 1] * sc, W1h, W1l);
        split_hl((bih[n] + bhh[n]) * sc, bsh, bsl);
        u32 be;
        if      (q == 0) be = pack_f16(W0h, W0l);
        else if (q == 1) be = pack_f16(W0h, W1h);
        else if (q == 2) be = pack_f16(W1l, W1h);
        else             be = pack_f16(bsh, bsl);
        B.be[nt] = be;
    }
}

// A_ext row m (16B): cols [x0h,x0h,x0l,x1h,x1h,x1l,1,1]
__device__ __forceinline__ void write_ext(char* e, int m, float x0, float x1){
    float x0h,x0l,x1h,x1l;
    split_hl(x0, x0h, x0l); split_hl(x1, x1h, x1l);
    uint4 v = make_uint4(pack_f16(x0h, x0h), pack_f16(x0l, x1h),
                         pack_f16(x1h, x1l), pack_f16(1.0f, 1.0f));
    *reinterpret_cast<uint4*>(e + m * 16) = v;
}

// ---- one 16-row m-tile: gates GEMM + ext term; result packed half2 (8 regs) ----
__device__ __forceinline__ void mma_tile(u32 pg[4][2], u32 ah_u, const char* extr,
                                         const Bregs& B, int mt8, int lrow, int lcol,
                                         int g, int q){
    float d[4][4];
#pragma unroll
    for (int nt = 0; nt < 4; nt++)
#pragma unroll
        for (int p = 0; p < 4; p++) d[nt][p] = 0.0f;
#pragma unroll
    for (int kt = 0; kt < 4; kt++){
        u32 a[4];
        ldmA(a, ah_u + (u32)((mt8 * 16 + lrow) * STRIDE + kt * 32 + lcol));
#pragma unroll
        for (int nt = 0; nt < 4; nt++) mma16816(d[nt], a, B.bh[kt][nt]);
    }
    const int row = mt8 * 16 + g;
    u32 ae[2];
    ae[0] = *(const u32*)(extr + row * 16 + q * 4);
    ae[1] = *(const u32*)(extr + (row + 8) * 16 + q * 4);
#pragma unroll
    for (int nt = 0; nt < 4; nt++) mma1688(d[nt], ae, B.be[nt]);
#pragma unroll
    for (int nt = 0; nt < 4; nt++){
        pg[nt][0] = pack_f16(d[nt][0], d[nt][1]);
        pg[nt][1] = pack_f16(d[nt][2], d[nt][3]);
    }
}

// ---- deferred epilogue: all-half2 activations + c update + packed h STS ----
__device__ __forceinline__ void epi_tile(const u32 pg[4][2], __half2 c2[2],
                                         char* ahw, int rowA, int col){
    const __half2 H05 = __floats2half2_rn(0.5f, 0.5f);
#pragma unroll
    for (int pr = 0; pr < 2; pr++){
        u32 ti = tanh2u(pg[0][pr]);
        u32 tf = tanh2u(pg[1][pr]);
        u32 tg = tanh2u(pg[2][pr]);
        u32 to = tanh2u(pg[3][pr]);
        __half2 si = __hfma2(u2h(ti), H05, H05);
        __half2 sf = __hfma2(u2h(tf), H05, H05);
        __half2 so = __hfma2(u2h(to), H05, H05);
        __half2 cc = __hfma2(sf, c2[pr], __hmul2(si, u2h(tg)));
        c2[pr] = cc;
        u32 tc = tanh2u(h2u(cc));
        __half2 hv = __hmul2(so, u2h(tc));
        *(u32*)(ahw + (rowA + pr * 8) * STRIDE + col) = h2u(hv);
    }
}

__global__ void __launch_bounds__(NT, 2)
lstm_hmma_kernel(const float* __restrict__ in,
                 const float* __restrict__ Wih_e, const float* __restrict__ Whh_e,
                 const float* __restrict__ bih_e, const float* __restrict__ bhh_e,
                 const float* __restrict__ Wih_d, const float* __restrict__ Whh_d,
                 const float* __restrict__ bih_d, const float* __restrict__ bhh_d,
                 const float* __restrict__ Wfc,   const float* __restrict__ bfc,
                 float* __restrict__ out)
{
    extern __shared__ char smc[];
    const int tid = threadIdx.x;
    const int lane = tid & 31, w = tid >> 5;
    const int q = lane & 3, g = lane >> 2;
    const int base = blockIdx.x * EPB;
    const u32 sb = smem_u32(smc);
    float2* wfc = (float2*)(smc + SM_WFC);

    const int lrow = lane & 15;
    const int lcol = (lane >> 4) * 16;
    const int col  = w * 16 + q * 4;

    // ---- init smem ----
    if (tid < 64) wfc[tid] = make_float2(Wfc[tid], Wfc[64 + tid]);
    {
        u32* z = (u32*)(smc + SM_AH);
        for (int i = tid; i < 2 * PL / 4; i += NT) z[i] = 0u;   // h0 = 0
    }
    if (tid < EPB){
        float2 xv = *(const float2*)(in + (size_t)(base + tid) * (TIN * 2));
        write_ext(smc + SM_EXT, tid, xv.x, xv.y);
    }
    Bregs B;
    load_B(B, Whh_e, Wih_e, bih_e, bhh_e, w, g, q);
    __half2 c2[16];
#pragma unroll
    for (int i = 0; i < 16; i++) c2[i] = __floats2half2_rn(0.0f, 0.0f);
    const float bfc0 = bfc[0], bfc1 = bfc[1];
    __syncthreads();

    for (int t = 0; t < TSTEPS; t++){
        const int rb = t & 1, wbuf = rb ^ 1;
        const u32 ah_u = sb + SM_AH + rb * PL;       // read plane (fp16 h)
        char* ahw = smc + SM_AH + wbuf * PL;          // write plane
        const char* extr = smc + SM_EXT + rb * 2048;
        char* extw = smc + SM_EXT + wbuf * 2048;
        const bool dec = (t >= TIN);

        // ---- software-pipelined 8 m-tiles: MMA(i) overlaps epilogue(i-1) ----
        u32 pg[2][4][2];
        mma_tile(pg[0], ah_u, extr, B, 0, lrow, lcol, g, q);
#pragma unroll
        for (int mt8 = 1; mt8 < 8; mt8++){
            mma_tile(pg[mt8 & 1], ah_u, extr, B, mt8, lrow, lcol, g, q);
            epi_tile(pg[(mt8 - 1) & 1], c2 + (mt8 - 1) * 2, ahw, (mt8 - 1) * 16 + g, col);
        }
        epi_tile(pg[1], c2 + 14, ahw, 7 * 16 + g, col);

        if (!dec){
            if (tid < EPB){
                const int xi = (t + 1 < TIN) ? t + 1 : TIN - 1;   // t=127 rewrites x_127 = dec_in0
                float2 xv = *(const float2*)(in + (size_t)(base + tid) * (TIN * 2) + (size_t)xi * 2);
                write_ext(extw, tid, xv.x, xv.y);
            }
            __syncthreads();
            if (t == TIN - 1) load_B(B, Whh_d, Wih_d, bih_d, bhh_d, w, g, q);
        } else {
            __syncthreads();                        // h_t plane complete
            // FC head: 2 threads per element, 32 dims each
            const int m = tid >> 1, half = tid & 1;
            const char* hp = ahw + m * STRIDE + half * 64;
            float p0 = 0.f, p1 = 0.f;
#pragma unroll
            for (int j = 0; j < 16; j++){
                u32 hh = *(const u32*)(hp + j * 4);
                __half2 hb = u2h(hh);
                float h0 = __half2float(hb.x);
                float h1 = __half2float(hb.y);
                const int k = half * 32 + j * 2;
                float2 wf0 = wfc[k], wf1 = wfc[k + 1];
                p0 += h0 * wf0.x + h1 * wf1.x;
                p1 += h0 * wf0.y + h1 * wf1.y;
            }
            p0 += __shfl_xor_sync(0xffffffffu, p0, 1);
            p1 += __shfl_xor_sync(0xffffffffu, p1, 1);
            if (half == 0){
                float s0 = fmaf(tanh_hw(0.5f * (p0 + bfc0)), 0.5f, 0.5f);
                float s1 = fmaf(tanh_hw(0.5f * (p1 + bfc1)), 0.5f, 0.5f);
                *(float2*)(out + (size_t)(base + m) * (TOUT * 2) + (size_t)(t - TIN) * 2)
                    = make_float2(s0, s1);
                if (t < TSTEPS - 1) write_ext(extw, m, s0, s1);   // autoregressive feedback
            }
            __syncthreads();
        }
    }
}

extern "C" void kernel_launch(void* const* d_in, const int* in_sizes, int n_in,
                              void* d_out, int out_size) {
    (void)n_in; (void)out_size;
    const float* in    = (const float*)d_in[0];
    const float* Wih_e = (const float*)d_in[1];
    const float* Whh_e = (const float*)d_in[2];
    const float* bih_e = (const float*)d_in[3];
    const float* bhh_e = (const float*)d_in[4];
    const float* Wih_d = (const float*)d_in[5];
    const float* Whh_d = (const float*)d_in[6];
    const float* bih_d = (const float*)d_in[7];
    const float* bhh_d = (const float*)d_in[8];
    const float* Wfc   = (const float*)d_in[9];
    const float* bfc   = (const float*)d_in[10];
    float* out = (float*)d_out;

    int B = in_sizes[0] / (TIN * 2);          // 131072
    int grid = B / EPB;                        // 1024 CTAs

    cudaFuncSetAttribute(lstm_hmma_kernel,
                         cudaFuncAttributeMaxDynamicSharedMemorySize, SM_TOTAL);
    lstm_hmma_kernel<<<grid, NT, SM_TOTAL>>>(
        in, Wih_e, Whh_e, bih_e, bhh_e,
        Wih_d, Whh_d, bih_d, bhh_d, Wfc, bfc, out);
}